// round 2
// baseline (speedup 1.0000x reference)
#include <cuda_runtime.h>

// FractionalSTFT_42253888258226
//
// Identity (established R1, rel_err=1.6e-7): the fractional grid k2={j/16}
// is uniform over a full period -> W^H W = 16 I -> pinv(W) W = I -> the whole
// STFT/iSTFT pipeline is out == x. Kernel = optimal 2 MiB D2D copy.
//
// R2: latency-optimized copy. 128 blocks x 256 threads, 4 independent
// float4 per thread (loads batched for MLP=4), exact coverage of
// 524288 floats = 131072 float4 = 128*256*4.

__global__ void __launch_bounds__(256, 1)
fstft_copy_kernel(const float4* __restrict__ src,
                  float4* __restrict__ dst,
                  int n_vec4) {
    // Each thread handles 4 float4, strided by total thread count so that
    // consecutive threads access consecutive 16B chunks (fully coalesced).
    int tid = blockIdx.x * blockDim.x + threadIdx.x;
    int stride = gridDim.x * blockDim.x;

    int i0 = tid;
    int i1 = tid + stride;
    int i2 = tid + 2 * stride;
    int i3 = tid + 3 * stride;

    if (i3 < n_vec4) {
        // fast path: no predication per access, 4 loads in flight
        float4 a = src[i0];
        float4 b = src[i1];
        float4 c = src[i2];
        float4 d = src[i3];
        dst[i0] = a;
        dst[i1] = b;
        dst[i2] = c;
        dst[i3] = d;
    } else {
        if (i0 < n_vec4) dst[i0] = src[i0];
        if (i1 < n_vec4) dst[i1] = src[i1];
        if (i2 < n_vec4) dst[i2] = src[i2];
    }
}

__global__ void fstft_copy_tail(const float* __restrict__ src,
                                float* __restrict__ dst,
                                int start, int n) {
    int i = start + blockIdx.x * blockDim.x + threadIdx.x;
    if (i < n) dst[i] = src[i];
}

extern "C" void kernel_launch(void* const* d_in, const int* in_sizes, int n_in,
                              void* d_out, int out_size) {
    const float* x = (const float*)d_in[0];   // (2, 2, 131072) fp32
    float* out = (float*)d_out;

    int n = out_size;                 // 524288
    if (n > in_sizes[0]) n = in_sizes[0];

    int n_vec4 = n >> 2;              // 131072 float4
    const int block = 256;
    const int per_thread = 4;
    int grid = (n_vec4 + block * per_thread - 1) / (block * per_thread);  // 128
    if (grid > 0) {
        fstft_copy_kernel<<<grid, block>>>((const float4*)x, (float4*)out, n_vec4);
    }

    int done = n_vec4 << 2;
    if (n - done > 0) {
        fstft_copy_tail<<<1, 128>>>(x, out, done, n);
    }
}